// round 16
// baseline (speedup 1.0000x reference)
#include <cuda_runtime.h>
#include <cuda_fp16.h>
#include <cstdint>

#define B_DIM   8192
#define N_IN    512
#define N_UNITS 2048
#define N_EXC   1024

#define TM      128
#define TN      128
#define KC      64              // K elements per chunk
#define NCH_P1  8               // 8*64 = 512  (x @ iw)
#define NCH_P2  16              // 16*64 = 1024 (recurrent)
#define NCHUNK  (NCH_P1 + NCH_P2)

#define OFF_AH      0
#define OFF_AL      16384
#define OFF_BH      32768
#define OFF_BL      49152
#define STAGE_B     65536
#define STAGES      3
#define SMEM_TOTAL  (STAGES * STAGE_B)   // 196608

#define INV2048     4.8828125e-4f

// ---------------- scratch (fp16 hi/lo splits) ----------------
__device__ __half g_Xh [B_DIM * N_IN];
__device__ __half g_Xl [B_DIM * N_IN];
__device__ __half g_Yeh[B_DIM * N_EXC];
__device__ __half g_Yel[B_DIM * N_EXC];
__device__ __half g_Yih[B_DIM * N_EXC];
__device__ __half g_Yil[B_DIM * N_EXC];
__device__ __half g_WXh[N_UNITS * N_IN];    // WX[n][k] = iw[k][n]
__device__ __half g_WXl[N_UNITS * N_IN];
__device__ __half g_Rh [N_UNITS * N_EXC];   // R[n][k]: n<1024 -> eiw[k][n]; else -> -eiw[n-1024][k]
__device__ __half g_Rl [N_UNITS * N_EXC];

// ---------------- helpers ----------------
__device__ __forceinline__ uint32_t smem_u32(const void* p) {
    uint32_t a;
    asm("{ .reg .u64 t; cvta.to.shared.u64 t, %1; cvt.u32.u64 %0, t; }" : "=r"(a) : "l"(p));
    return a;
}

__device__ __forceinline__ void cpa16(uint32_t dst, const void* src) {
    asm volatile("cp.async.cg.shared.global [%0], [%1], 16;" :: "r"(dst), "l"(src));
}

__device__ __forceinline__ void ldsm4(uint32_t* r, uint32_t addr) {
    asm volatile("ldmatrix.sync.aligned.m8n8.x4.shared.b16 {%0,%1,%2,%3}, [%4];"
        : "=r"(r[0]), "=r"(r[1]), "=r"(r[2]), "=r"(r[3]) : "r"(addr));
}

// fp32-accumulate MMA (hi*hi)
__device__ __forceinline__ void mma16816(float* d, const uint32_t* a, const uint32_t* b) {
    asm volatile("mma.sync.aligned.m16n8k16.row.col.f32.f16.f16.f32 "
        "{%0,%1,%2,%3}, {%4,%5,%6,%7}, {%8,%9}, {%0,%1,%2,%3};"
        : "+f"(d[0]), "+f"(d[1]), "+f"(d[2]), "+f"(d[3])
        : "r"(a[0]), "r"(a[1]), "r"(a[2]), "r"(a[3]), "r"(b[0]), "r"(b[1]));
}

// fp16-accumulate MMA (correction terms; D/C packed half2 x2)
__device__ __forceinline__ void mma16816h(uint32_t* d, const uint32_t* a, const uint32_t* b) {
    asm volatile("mma.sync.aligned.m16n8k16.row.col.f16.f16.f16.f16 "
        "{%0,%1}, {%2,%3,%4,%5}, {%6,%7}, {%0,%1};"
        : "+r"(d[0]), "+r"(d[1])
        : "r"(a[0]), "r"(a[1]), "r"(a[2]), "r"(a[3]), "r"(b[0]), "r"(b[1]));
}

// ---------------- pre-pass: fp32 -> (fp16 hi, fp16 lo*2048) ----------------
__device__ __forceinline__ void split2(float v, __half& h, __half& l) {
    __half hh = __float2half_rn(v);
    float r = (v - __half2float(hh)) * 2048.0f;
    h = hh;
    l = __float2half_rn(r);
}

__device__ __forceinline__ void split4_store(float4 v, __half* hp, __half* lp, int e0) {
    __half h0, h1, h2, h3, l0, l1, l2, l3;
    split2(v.x, h0, l0); split2(v.y, h1, l1);
    split2(v.z, h2, l2); split2(v.w, h3, l3);
    __half2 hh01 = __halves2half2(h0, h1), hh23 = __halves2half2(h2, h3);
    __half2 ll01 = __halves2half2(l0, l1), ll23 = __halves2half2(l2, l3);
    uint2 hw, lw;
    hw.x = *(uint32_t*)&hh01; hw.y = *(uint32_t*)&hh23;
    lw.x = *(uint32_t*)&ll01; lw.y = *(uint32_t*)&ll23;
    *(uint2*)(hp + e0) = hw;
    *(uint2*)(lp + e0) = lw;
}

__global__ void split_acts_kernel(const float4* __restrict__ x4,
                                  const float4* __restrict__ ye4,
                                  const float4* __restrict__ yi4) {
    int i = blockIdx.x * 256 + threadIdx.x;          // float4 index
    if (i < B_DIM * N_IN / 4)  split4_store(x4[i],  g_Xh,  g_Xl,  i * 4);
    if (i < B_DIM * N_EXC / 4) {
        split4_store(ye4[i], g_Yeh, g_Yel, i * 4);
        split4_store(yi4[i], g_Yih, g_Yil, i * 4);
    }
}

// iw [512 x 2048] -> WX[n][k] (transposed), tiled through smem, coalesced both sides
__global__ void split_wx_kernel(const float* __restrict__ iw) {
    __shared__ float t[32][33];
    const int k0 = blockIdx.x * 32, n0 = blockIdx.y * 32;
    const int c = threadIdx.x & 31, r4 = threadIdx.x >> 5;
    #pragma unroll
    for (int i = 0; i < 4; i++) {
        int r = r4 * 4 + i;
        t[r][c] = iw[(size_t)(k0 + r) * N_UNITS + n0 + c];
    }
    __syncthreads();
    #pragma unroll
    for (int i = 0; i < 4; i++) {
        int r = r4 * 4 + i;                     // output row n = n0+r, col k = k0+c
        __half h, l; split2(t[c][r], h, l);
        g_WXh[(size_t)(n0 + r) * N_IN + k0 + c] = h;
        g_WXl[(size_t)(n0 + r) * N_IN + k0 + c] = l;
    }
}

// eiw [1024 x 1024] -> exc half transposed, inh half direct-negated
__global__ void split_r_kernel(const float* __restrict__ eiw) {
    __shared__ float t[32][33];
    const int k0 = blockIdx.x * 32, j0 = blockIdx.y * 32;
    const int c = threadIdx.x & 31, r4 = threadIdx.x >> 5;
    #pragma unroll
    for (int i = 0; i < 4; i++) {
        int r = r4 * 4 + i;
        float v = eiw[(size_t)(j0 + r) * N_EXC + k0 + c];
        t[r][c] = v;
        __half h, l; split2(-v, h, l);          // inh: R[1024+j][k] = -eiw[j][k] (coalesced)
        g_Rh[(size_t)(N_EXC + j0 + r) * N_EXC + k0 + c] = h;
        g_Rl[(size_t)(N_EXC + j0 + r) * N_EXC + k0 + c] = l;
    }
    __syncthreads();
    #pragma unroll
    for (int i = 0; i < 4; i++) {
        int r = r4 * 4 + i;                     // exc: R[k0+r][j0+c] = eiw[j0+c][k0+r]
        __half h, l; split2(t[c][r], h, l);
        g_Rh[(size_t)(k0 + r) * N_EXC + j0 + c] = h;
        g_Rl[(size_t)(k0 + r) * N_EXC + j0 + c] = l;
    }
}

// ---------------- main fused HMMA kernel (8 warps, 64x32 warp tiles) ----------------
__global__ __launch_bounds__(256, 1)
void eisnu_hmma_kernel(const float* __restrict__ y_exc, const float* __restrict__ s_exc,
                       const float* __restrict__ y_inh, const float* __restrict__ s_inh,
                       const float* __restrict__ bvec,  const float* __restrict__ lvec,
                       float* __restrict__ out)
{
    extern __shared__ char smem[];
    const uint32_t sb = smem_u32(smem);

    const int tid  = threadIdx.x;
    const int lane = tid & 31;
    const int wid  = tid >> 5;        // 0..7
    const int wm   = wid >> 2;        // 0..1 -> 64-row warp block
    const int wn   = wid & 3;         // 0..3 -> 32-col warp block
    const int m0   = blockIdx.y * TM;
    const int n0   = blockIdx.x * TN;
    const bool is_exc = (n0 < N_EXC);

    float    acc0[4][4][4];   // hi*hi (fp32)     : 4 m16-tiles x 4 n8-tiles
    uint32_t acc1[4][4][2];   // corrections (fp16 packed, lo scaled by 2048)
    #pragma unroll
    for (int mt = 0; mt < 4; mt++)
        #pragma unroll
        for (int nt = 0; nt < 4; nt++) {
            #pragma unroll
            for (int q = 0; q < 4; q++) acc0[mt][nt][q] = 0.0f;
            acc1[mt][nt][0] = 0u; acc1[mt][nt][1] = 0u;
        }

    const __half* ysel_h = is_exc ? g_Yih : g_Yeh;
    const __half* ysel_l = is_exc ? g_Yil : g_Yel;

    // ---- chunk loader (cp.async into stage slot c%3), 256 threads ----
    auto load_chunk = [&](int c) {
        const __half *pAh, *pAl, *pBh, *pBl;
        int lda, kb;
        if (c < NCH_P1) {
            kb = c * KC; lda = N_IN;
            pAh = g_Xh; pAl = g_Xl; pBh = g_WXh; pBl = g_WXl;
        } else {
            kb = (c - NCH_P1) * KC; lda = N_EXC;
            pAh = ysel_h; pAl = ysel_l; pBh = g_Rh; pBl = g_Rl;
        }
        const uint32_t stb = sb + (uint32_t)(c % STAGES) * STAGE_B;
        #pragma unroll
        for (int i = 0; i < 4; i++) {
            int s   = tid + i * 256;
            int row = s >> 3;
            int cc  = s & 7;
            uint32_t dsto = (uint32_t)row * 128 + (uint32_t)((cc ^ (row & 7)) << 4);
            size_t aoff = (size_t)(m0 + row) * lda + kb + cc * 8;
            cpa16(stb + OFF_AH + dsto, pAh + aoff);
            cpa16(stb + OFF_AL + dsto, pAl + aoff);
        }
        #pragma unroll
        for (int i = 0; i < 4; i++) {
            int s   = tid + i * 256;
            int row = s >> 3;
            int cc  = s & 7;
            uint32_t dsto = (uint32_t)row * 128 + (uint32_t)((cc ^ (row & 7)) << 4);
            size_t boff = (size_t)(n0 + row) * lda + kb + cc * 8;
            cpa16(stb + OFF_BH + dsto, pBh + boff);
            cpa16(stb + OFF_BL + dsto, pBl + boff);
        }
        asm volatile("cp.async.commit_group;" ::: "memory");
    };

    // ---- ldmatrix lane addressing (chunk-relative) ----
    const int arow_base = wm * 64 + (lane & 7) + ((lane >> 3) & 1) * 8;   // + mt*16
    const int akh       = (lane >> 4) & 1;                                 // k-half (x8)
    const int g         = lane >> 3;
    const int brow_base = wn * 32 + (lane & 7) + ((g >> 1) << 3);          // + p*16
    const int bkh       = g & 1;

    // fragment loaders
    auto lda_hi = [&](uint32_t stb, int kk, uint32_t (*ahp)[4], uint32_t (*bhp)[2]) {
        #pragma unroll
        for (int mt = 0; mt < 4; mt++) {
            int row = arow_base + mt * 16;
            int cchunk = kk * 2 + akh;
            uint32_t addr = stb + (uint32_t)row * 128 +
                            (uint32_t)((cchunk ^ (row & 7)) << 4);
            ldsm4(ahp[mt], addr + OFF_AH);
        }
        #pragma unroll
        for (int p = 0; p < 2; p++) {
            int row = brow_base + p * 16;
            int cchunk = kk * 2 + bkh;
            uint32_t addr = stb + (uint32_t)row * 128 +
                            (uint32_t)((cchunk ^ (row & 7)) << 4);
            uint32_t r4[4];
            ldsm4(r4, addr + OFF_BH);
            bhp[p * 2 + 0][0] = r4[0]; bhp[p * 2 + 0][1] = r4[1];
            bhp[p * 2 + 1][0] = r4[2]; bhp[p * 2 + 1][1] = r4[3];
        }
    };
    auto lda_lo = [&](uint32_t stb, int kk, uint32_t (*alp)[4], uint32_t (*blp)[2]) {
        #pragma unroll
        for (int mt = 0; mt < 4; mt++) {
            int row = arow_base + mt * 16;
            int cchunk = kk * 2 + akh;
            uint32_t addr = stb + (uint32_t)row * 128 +
                            (uint32_t)((cchunk ^ (row & 7)) << 4);
            ldsm4(alp[mt], addr + OFF_AL);
        }
        #pragma unroll
        for (int p = 0; p < 2; p++) {
            int row = brow_base + p * 16;
            int cchunk = kk * 2 + bkh;
            uint32_t addr = stb + (uint32_t)row * 128 +
                            (uint32_t)((cchunk ^ (row & 7)) << 4);
            uint32_t r4[4];
            ldsm4(r4, addr + OFF_BL);
            blp[p * 2 + 0][0] = r4[0]; blp[p * 2 + 0][1] = r4[1];
            blp[p * 2 + 1][0] = r4[2]; blp[p * 2 + 1][1] = r4[3];
        }
    };

    // ---- 3-stage pipeline, one barrier per chunk ----
    load_chunk(0);
    load_chunk(1);

    for (int c = 0; c < NCHUNK; c++) {
        if (c < NCHUNK - 1) {
            asm volatile("cp.async.wait_group 1;" ::: "memory");
        } else {
            asm volatile("cp.async.wait_group 0;" ::: "memory");
        }
        __syncthreads();                       // all threads' chunk-c data visible
        if (c + 2 < NCHUNK) load_chunk(c + 2); // overwrites slot of c-1 (sealed by sync)

        const uint32_t stb = sb + (uint32_t)(c % STAGES) * STAGE_B;

        uint32_t ah[2][4][4], bh[2][4][2];     // double-buffered hi fragments
        uint32_t al[4][4],    bl[4][2];        // single-buffered lo fragments

        lda_hi(stb, 0, ah[0], bh[0]);

        #pragma unroll
        for (int kk = 0; kk < 4; kk++) {
            const int cur = kk & 1;
            const int nxt = cur ^ 1;
            if (kk < 3) lda_hi(stb, kk + 1, ah[nxt], bh[nxt]);   // prefetch next-kk hi
            lda_lo(stb, kk, al, bl);                              // just-in-time lo

            #pragma unroll
            for (int mt = 0; mt < 4; mt++)
                #pragma unroll
                for (int nt = 0; nt < 4; nt++)
                    mma16816(acc0[mt][nt], ah[cur][mt], bh[cur][nt]);  // hi*hi
            #pragma unroll
            for (int mt = 0; mt < 4; mt++)
                #pragma unroll
                for (int nt = 0; nt < 4; nt++)
                    mma16816h(acc1[mt][nt], al[mt], bh[cur][nt]);      // lo*hi
            #pragma unroll
            for (int mt = 0; mt < 4; mt++)
                #pragma unroll
                for (int nt = 0; nt < 4; nt++)
                    mma16816h(acc1[mt][nt], ah[cur][mt], bl[nt]);      // hi*lo
        }
    }

    // ---- fused epilogue ----
    const float* y_in = is_exc ? y_exc : y_inh;
    const float* s_in = is_exc ? s_exc : s_inh;
    const size_t HALF = (size_t)B_DIM * N_EXC;
    float* y_out = out + (is_exc ? (size_t)0 : 2 * HALF);
    float* s_out = out + (is_exc ? HALF : 3 * HALF);

    #pragma unroll
    for (int mt = 0; mt < 4; mt++) {
        #pragma unroll
        for (int nt = 0; nt < 4; nt++) {
            const int cg  = n0 + wn * 32 + nt * 8 + 2 * (lane & 3);   // global col
            const int cl  = cg - (is_exc ? 0 : N_EXC);                 // col in half
            const float l0 = lvec[cg],     l1 = lvec[cg + 1];
            const float b0 = bvec[cg],     b1 = bvec[cg + 1];
            #pragma unroll
            for (int h = 0; h < 2; h++) {                              // row halves (+0, +8)
                const int r = m0 + wm * 64 + mt * 16 + (lane >> 2) + h * 8;
                const half2 c1 = *(const half2*)&acc1[mt][nt][h];
                const float v0 = acc0[mt][nt][2 * h + 0] + INV2048 * __low2float(c1);
                const float v1 = acc0[mt][nt][2 * h + 1] + INV2048 * __high2float(c1);
                const float2 yv = *(const float2*)(y_in + (size_t)r * N_EXC + cl);
                const float2 sv = *(const float2*)(s_in + (size_t)r * N_EXC + cl);
                float z0 = v0 + yv.x + l0 * sv.x * (1.0f - yv.x);
                float z1 = v1 + yv.y + l1 * sv.y * (1.0f - yv.y);
                float sn0 = fmaxf(z0, 0.0f), sn1 = fmaxf(z1, 0.0f);
                float2 sw2 = make_float2(sn0, sn1);
                float2 yw2 = make_float2((sn0 + b0 > 0.0f) ? 1.0f : 0.0f,
                                         (sn1 + b1 > 0.0f) ? 1.0f : 0.0f);
                *(float2*)(s_out + (size_t)r * N_EXC + cl) = sw2;
                *(float2*)(y_out + (size_t)r * N_EXC + cl) = yw2;
            }
        }
    }
}

// ---------------- launch ----------------
extern "C" void kernel_launch(void* const* d_in, const int* in_sizes, int n_in,
                              void* d_out, int out_size)
{
    const float* x_t   = (const float*)d_in[0];
    const float* y_exc = (const float*)d_in[1];
    const float* s_exc = (const float*)d_in[2];
    const float* y_inh = (const float*)d_in[3];
    const float* s_inh = (const float*)d_in[4];
    const float* iw    = (const float*)d_in[5];
    const float* eiw   = (const float*)d_in[6];
    const float* b     = (const float*)d_in[7];
    const float* l     = (const float*)d_in[8];
    float* out = (float*)d_out;

    split_acts_kernel<<<(B_DIM * N_EXC / 4 + 255) / 256, 256>>>(
        (const float4*)x_t, (const float4*)y_exc, (const float4*)y_inh);
    split_wx_kernel<<<dim3(N_IN / 32, N_UNITS / 32), 256>>>(iw);
    split_r_kernel<<<dim3(N_EXC / 32, N_EXC / 32), 256>>>(eiw);

    cudaFuncSetAttribute(eisnu_hmma_kernel,
                         cudaFuncAttributeMaxDynamicSharedMemorySize, SMEM_TOTAL);
    dim3 grid(N_UNITS / TN, B_DIM / TM);   // 16 x 64 = 1024 CTAs
    eisnu_hmma_kernel<<<grid, 256, SMEM_TOTAL>>>(y_exc, s_exc, y_inh, s_inh, b, l, out);
}

// round 17
// speedup vs baseline: 1.5084x; 1.5084x over previous
#include <cuda_runtime.h>
#include <cuda_fp16.h>
#include <cstdint>

#define B_DIM   8192
#define N_IN    512
#define N_UNITS 2048
#define N_EXC   1024

#define TM      128
#define TN      128
#define KC      64              // K elements per chunk
#define NCH_P1  8               // 8*64 = 512  (x @ iw)
#define NCH_P2  16              // 16*64 = 1024 (recurrent)
#define NCHUNK  (NCH_P1 + NCH_P2)

#define OFF_AH      0
#define OFF_AL      16384
#define OFF_BH      32768
#define OFF_BL      49152
#define STAGE_B     65536
#define STAGES      3
#define SMEM_TOTAL  (STAGES * STAGE_B)   // 196608

#define INV2048     4.8828125e-4f

// ---------------- scratch (fp16 hi/lo splits) ----------------
__device__ __half g_Xh [B_DIM * N_IN];
__device__ __half g_Xl [B_DIM * N_IN];
__device__ __half g_Yeh[B_DIM * N_EXC];
__device__ __half g_Yel[B_DIM * N_EXC];
__device__ __half g_Yih[B_DIM * N_EXC];
__device__ __half g_Yil[B_DIM * N_EXC];
__device__ __half g_WXh[N_UNITS * N_IN];    // WX[n][k] = iw[k][n]
__device__ __half g_WXl[N_UNITS * N_IN];
__device__ __half g_Rh [N_UNITS * N_EXC];   // R[n][k]: n<1024 -> eiw[k][n]; else -> -eiw[n-1024][k]
__device__ __half g_Rl [N_UNITS * N_EXC];

// ---------------- helpers ----------------
__device__ __forceinline__ uint32_t smem_u32(const void* p) {
    uint32_t a;
    asm("{ .reg .u64 t; cvta.to.shared.u64 t, %1; cvt.u32.u64 %0, t; }" : "=r"(a) : "l"(p));
    return a;
}

__device__ __forceinline__ void cpa16(uint32_t dst, const void* src) {
    asm volatile("cp.async.cg.shared.global [%0], [%1], 16;" :: "r"(dst), "l"(src));
}

__device__ __forceinline__ void ldsm4(uint32_t* r, uint32_t addr) {
    asm volatile("ldmatrix.sync.aligned.m8n8.x4.shared.b16 {%0,%1,%2,%3}, [%4];"
        : "=r"(r[0]), "=r"(r[1]), "=r"(r[2]), "=r"(r[3]) : "r"(addr));
}

__device__ __forceinline__ void mma16816(float* d, const uint32_t* a, const uint32_t* b) {
    asm volatile("mma.sync.aligned.m16n8k16.row.col.f32.f16.f16.f32 "
        "{%0,%1,%2,%3}, {%4,%5,%6,%7}, {%8,%9}, {%0,%1,%2,%3};"
        : "+f"(d[0]), "+f"(d[1]), "+f"(d[2]), "+f"(d[3])
        : "r"(a[0]), "r"(a[1]), "r"(a[2]), "r"(a[3]), "r"(b[0]), "r"(b[1]));
}

// ---------------- pre-pass: fp32 -> (fp16 hi, fp16 lo*2048) ----------------
__device__ __forceinline__ void split2(float v, __half& h, __half& l) {
    __half hh = __float2half_rn(v);
    float r = (v - __half2float(hh)) * 2048.0f;
    h = hh;
    l = __float2half_rn(r);
}

__device__ __forceinline__ void split4_store(float4 v, __half* hp, __half* lp, int e0) {
    __half h0, h1, h2, h3, l0, l1, l2, l3;
    split2(v.x, h0, l0); split2(v.y, h1, l1);
    split2(v.z, h2, l2); split2(v.w, h3, l3);
    __half2 hh01 = __halves2half2(h0, h1), hh23 = __halves2half2(h2, h3);
    __half2 ll01 = __halves2half2(l0, l1), ll23 = __halves2half2(l2, l3);
    uint2 hw, lw;
    hw.x = *(uint32_t*)&hh01; hw.y = *(uint32_t*)&hh23;
    lw.x = *(uint32_t*)&ll01; lw.y = *(uint32_t*)&ll23;
    *(uint2*)(hp + e0) = hw;
    *(uint2*)(lp + e0) = lw;
}

// Merged pre-pass: one launch, three independent regions proceed concurrently.
// Region 0: [0, NB_ACTS)           acts (x, y_exc, y_inh) elementwise split, float4
// Region 1: [NB_ACTS, +NB_WX)      iw transpose-split (32x32 tiles)
// Region 2: [NB_ACTS+NB_WX, +NB_R) eiw transpose-split + negated direct copy
#define NB_ACTS (B_DIM * N_EXC / 4 / 256)            // 8192
#define NB_WX   ((N_IN / 32) * (N_UNITS / 32))       // 16*64 = 1024
#define NB_R    ((N_EXC / 32) * (N_EXC / 32))        // 32*32 = 1024

__global__ void split_all_kernel(const float* __restrict__ x_t,
                                 const float* __restrict__ y_exc,
                                 const float* __restrict__ y_inh,
                                 const float* __restrict__ iw,
                                 const float* __restrict__ eiw) {
    const int bid = blockIdx.x;

    if (bid < NB_ACTS) {
        int i = bid * 256 + threadIdx.x;             // float4 index
        if (i < B_DIM * N_IN / 4)
            split4_store(((const float4*)x_t)[i], g_Xh, g_Xl, i * 4);
        split4_store(((const float4*)y_exc)[i], g_Yeh, g_Yel, i * 4);
        split4_store(((const float4*)y_inh)[i], g_Yih, g_Yil, i * 4);
        return;
    }

    __shared__ float t[32][33];
    const int c = threadIdx.x & 31, r4 = threadIdx.x >> 5;

    if (bid < NB_ACTS + NB_WX) {
        // iw [512 x 2048] -> WX[n][k] transposed
        const int tb = bid - NB_ACTS;
        const int k0 = (tb % (N_IN / 32)) * 32;
        const int n0 = (tb / (N_IN / 32)) * 32;
        #pragma unroll
        for (int i = 0; i < 4; i++) {
            int r = r4 * 4 + i;
            t[r][c] = iw[(size_t)(k0 + r) * N_UNITS + n0 + c];
        }
        __syncthreads();
        #pragma unroll
        for (int i = 0; i < 4; i++) {
            int r = r4 * 4 + i;
            __half h, l; split2(t[c][r], h, l);
            g_WXh[(size_t)(n0 + r) * N_IN + k0 + c] = h;
            g_WXl[(size_t)(n0 + r) * N_IN + k0 + c] = l;
        }
    } else {
        // eiw [1024 x 1024] -> exc half transposed, inh half direct-negated
        const int tb = bid - NB_ACTS - NB_WX;
        const int k0 = (tb % (N_EXC / 32)) * 32;
        const int j0 = (tb / (N_EXC / 32)) * 32;
        #pragma unroll
        for (int i = 0; i < 4; i++) {
            int r = r4 * 4 + i;
            float v = eiw[(size_t)(j0 + r) * N_EXC + k0 + c];
            t[r][c] = v;
            __half h, l; split2(-v, h, l);       // inh: R[1024+j][k] = -eiw[j][k]
            g_Rh[(size_t)(N_EXC + j0 + r) * N_EXC + k0 + c] = h;
            g_Rl[(size_t)(N_EXC + j0 + r) * N_EXC + k0 + c] = l;
        }
        __syncthreads();
        #pragma unroll
        for (int i = 0; i < 4; i++) {
            int r = r4 * 4 + i;                  // exc: R[k0+r][j0+c] = eiw[j0+c][k0+r]
            __half h, l; split2(t[c][r], h, l);
            g_Rh[(size_t)(k0 + r) * N_EXC + j0 + c] = h;
            g_Rl[(size_t)(k0 + r) * N_EXC + j0 + c] = l;
        }
    }
}

// ---------------- main fused HMMA kernel (R7 structure, best measured) ----------------
__global__ __launch_bounds__(512, 1)
void eisnu_hmma_kernel(const float* __restrict__ y_exc, const float* __restrict__ s_exc,
                       const float* __restrict__ y_inh, const float* __restrict__ s_inh,
                       const float* __restrict__ bvec,  const float* __restrict__ lvec,
                       float* __restrict__ out)
{
    extern __shared__ char smem[];
    const uint32_t sb = smem_u32(smem);

    const int tid  = threadIdx.x;
    const int lane = tid & 31;
    const int wid  = tid >> 5;
    const int wm   = wid >> 2;        // 0..3 -> warp row block (32 rows)
    const int wn   = wid & 3;         // 0..3 -> warp col block (32 cols)
    const int m0   = blockIdx.y * TM;
    const int n0   = blockIdx.x * TN;
    const bool is_exc = (n0 < N_EXC);

    float acc0[2][4][4];   // hi*hi
    float acc1[2][4][4];   // hi*lo + lo*hi  (lo scaled by 2048)
    #pragma unroll
    for (int mt = 0; mt < 2; mt++)
        #pragma unroll
        for (int nt = 0; nt < 4; nt++)
            #pragma unroll
            for (int q = 0; q < 4; q++) { acc0[mt][nt][q] = 0.0f; acc1[mt][nt][q] = 0.0f; }

    const __half* ysel_h = is_exc ? g_Yih : g_Yeh;
    const __half* ysel_l = is_exc ? g_Yil : g_Yel;

    // ---- chunk loader (cp.async into stage slot c%3) ----
    auto load_chunk = [&](int c) {
        const __half *pAh, *pAl, *pBh, *pBl;
        int lda, kb;
        if (c < NCH_P1) {
            kb = c * KC; lda = N_IN;
            pAh = g_Xh; pAl = g_Xl; pBh = g_WXh; pBl = g_WXl;
        } else {
            kb = (c - NCH_P1) * KC; lda = N_EXC;
            pAh = ysel_h; pAl = ysel_l; pBh = g_Rh; pBl = g_Rl;
        }
        const uint32_t stb = sb + (uint32_t)(c % STAGES) * STAGE_B;
        #pragma unroll
        for (int i = 0; i < 2; i++) {
            int s   = tid + i * 512;
            int row = s >> 3;
            int cc  = s & 7;
            uint32_t dsto = (uint32_t)row * 128 + (uint32_t)((cc ^ (row & 7)) << 4);
            size_t aoff = (size_t)(m0 + row) * lda + kb + cc * 8;
            size_t boff = (size_t)(n0 + row) * lda + kb + cc * 8;
            cpa16(stb + OFF_AH + dsto, pAh + aoff);
            cpa16(stb + OFF_AL + dsto, pAl + aoff);
            cpa16(stb + OFF_BH + dsto, pBh + boff);
            cpa16(stb + OFF_BL + dsto, pBl + boff);
        }
        asm volatile("cp.async.commit_group;" ::: "memory");
    };

    // ---- precompute ldmatrix lane addressing (chunk-relative) ----
    const int arow_base = wm * 32 + (lane & 7) + ((lane >> 3) & 1) * 8;   // + mt*16
    const int akh       = (lane >> 4) & 1;                                 // k-half (x8)
    const int g         = lane >> 3;
    const int brow_base = wn * 32 + (lane & 7) + ((g >> 1) << 3);          // + p*16
    const int bkh       = g & 1;

    // ---- 3-stage pipeline, one barrier per chunk ----
    load_chunk(0);
    load_chunk(1);

    for (int c = 0; c < NCHUNK; c++) {
        if (c < NCHUNK - 1) {
            asm volatile("cp.async.wait_group 1;" ::: "memory");
        } else {
            asm volatile("cp.async.wait_group 0;" ::: "memory");
        }
        __syncthreads();                       // all threads' chunk-c data visible
        if (c + 2 < NCHUNK) load_chunk(c + 2); // overwrites slot of c-1 (sealed by sync)

        const uint32_t stb = sb + (uint32_t)(c % STAGES) * STAGE_B;

        #pragma unroll
        for (int kk = 0; kk < 4; kk++) {
            uint32_t ah[2][4], al[2][4], bh[4][2], bl[4][2];

            #pragma unroll
            for (int mt = 0; mt < 2; mt++) {
                int row = arow_base + mt * 16;
                int cchunk = kk * 2 + akh;
                uint32_t addr = stb + (uint32_t)row * 128 +
                                (uint32_t)((cchunk ^ (row & 7)) << 4);
                ldsm4(ah[mt], addr + OFF_AH);
                ldsm4(al[mt], addr + OFF_AL);
            }
            #pragma unroll
            for (int p = 0; p < 2; p++) {
                int row = brow_base + p * 16;
                int cchunk = kk * 2 + bkh;
                uint32_t addr = stb + (uint32_t)row * 128 +
                                (uint32_t)((cchunk ^ (row & 7)) << 4);
                uint32_t r4[4];
                ldsm4(r4, addr + OFF_BH);
                bh[p * 2 + 0][0] = r4[0]; bh[p * 2 + 0][1] = r4[1];
                bh[p * 2 + 1][0] = r4[2]; bh[p * 2 + 1][1] = r4[3];
                ldsm4(r4, addr + OFF_BL);
                bl[p * 2 + 0][0] = r4[0]; bl[p * 2 + 0][1] = r4[1];
                bl[p * 2 + 1][0] = r4[2]; bl[p * 2 + 1][1] = r4[3];
            }

            #pragma unroll
            for (int mt = 0; mt < 2; mt++)
                #pragma unroll
                for (int nt = 0; nt < 4; nt++) {
                    mma16816(acc0[mt][nt], ah[mt], bh[nt]);   // hi*hi
                    mma16816(acc1[mt][nt], ah[mt], bl[nt]);   // hi*lo
                    mma16816(acc1[mt][nt], al[mt], bh[nt]);   // lo*hi
                }
        }
    }

    // ---- fused epilogue ----
    const float* y_in = is_exc ? y_exc : y_inh;
    const float* s_in = is_exc ? s_exc : s_inh;
    const size_t HALF = (size_t)B_DIM * N_EXC;
    float* y_out = out + (is_exc ? (size_t)0 : 2 * HALF);
    float* s_out = out + (is_exc ? HALF : 3 * HALF);

    #pragma unroll
    for (int mt = 0; mt < 2; mt++) {
        #pragma unroll
        for (int nt = 0; nt < 4; nt++) {
            const int cg  = n0 + wn * 32 + nt * 8 + 2 * (lane & 3);   // global col
            const int cl  = cg - (is_exc ? 0 : N_EXC);                 // col in half
            const float l0 = lvec[cg],     l1 = lvec[cg + 1];
            const float b0 = bvec[cg],     b1 = bvec[cg + 1];
            #pragma unroll
            for (int h = 0; h < 2; h++) {                              // row halves (+0, +8)
                const int r = m0 + wm * 32 + mt * 16 + (lane >> 2) + h * 8;
                const float v0 = acc0[mt][nt][2 * h + 0] + INV2048 * acc1[mt][nt][2 * h + 0];
                const float v1 = acc0[mt][nt][2 * h + 1] + INV2048 * acc1[mt][nt][2 * h + 1];
                const float2 yv = *(const float2*)(y_in + (size_t)r * N_EXC + cl);
                const float2 sv = *(const float2*)(s_in + (size_t)r * N_EXC + cl);
                float z0 = v0 + yv.x + l0 * sv.x * (1.0f - yv.x);
                float z1 = v1 + yv.y + l1 * sv.y * (1.0f - yv.y);
                float sn0 = fmaxf(z0, 0.0f), sn1 = fmaxf(z1, 0.0f);
                float2 sw2 = make_float2(sn0, sn1);
                float2 yw2 = make_float2((sn0 + b0 > 0.0f) ? 1.0f : 0.0f,
                                         (sn1 + b1 > 0.0f) ? 1.0f : 0.0f);
                *(float2*)(s_out + (size_t)r * N_EXC + cl) = sw2;
                *(float2*)(y_out + (size_t)r * N_EXC + cl) = yw2;
            }
        }
    }
}

// ---------------- launch ----------------
extern "C" void kernel_launch(void* const* d_in, const int* in_sizes, int n_in,
                              void* d_out, int out_size)
{
    const float* x_t   = (const float*)d_in[0];
    const float* y_exc = (const float*)d_in[1];
    const float* s_exc = (const float*)d_in[2];
    const float* y_inh = (const float*)d_in[3];
    const float* s_inh = (const float*)d_in[4];
    const float* iw    = (const float*)d_in[5];
    const float* eiw   = (const float*)d_in[6];
    const float* b     = (const float*)d_in[7];
    const float* l     = (const float*)d_in[8];
    float* out = (float*)d_out;

    split_all_kernel<<<NB_ACTS + NB_WX + NB_R, 256>>>(x_t, y_exc, y_inh, iw, eiw);

    cudaFuncSetAttribute(eisnu_hmma_kernel,
                         cudaFuncAttributeMaxDynamicSharedMemorySize, SMEM_TOTAL);
    dim3 grid(N_UNITS / TN, B_DIM / TM);   // 16 x 64 = 1024 CTAs
    eisnu_hmma_kernel<<<grid, 512, SMEM_TOTAL>>>(y_exc, s_exc, y_inh, s_inh, b, l, out);
}